// round 8
// baseline (speedup 1.0000x reference)
#include <cuda_runtime.h>

// SplineLoss on GB300: reference samples the spline only at integer knot
// times (t = 0,10,...,1020) where dx == 0.0 exactly, so all moment terms
// vanish: loss == mean over s,b,d of (true[b,10s,d]-pred[b,10s,d])^2.
//
// R8: floor-probing refinements on the R6/R7 structure:
//  - 412 blocks x 512 thr (same 210944 threads / 1 float4-pair each):
//    halves the number of block tails and atomics
//  - ld.global.nc with L2::256B granule hint (rows are exactly 256B):
//    better DRAM page efficiency on cold pass
//  - two-level deterministic fixed-point atomic (4 bins x 103 + final fold)

#define T_ 1024
#define D4_ 16                   // 64 floats per row = 16 float4
#define S_ 103                   // sample times 0,10,...,1020
#define ROW_STRIDE4_ (T_ * D4_)  // float4 stride between batches
#define COUNT_ 843776.0          // 128 * 103 * 64
#define FIX_SCALE 16777216.0     // 2^24

constexpr int NBLK  = 4 * S_;    // 412 blocks, 4 per sample time
constexpr int NTHR  = 512;       // 32 batches x 16 float4
constexpr int NBINS = 4;
constexpr int BINSZ = NBLK / NBINS;   // 103

__device__ __align__(256) unsigned long long g_bins[NBINS * 32]; // use [i*32]
__device__ __align__(256) unsigned long long g_final = 0;

__device__ __forceinline__ float4 ldg_256b(const float4* p) {
    float4 v;
    asm volatile("ld.global.nc.L2::256B.v4.f32 {%0,%1,%2,%3}, [%4];"
                 : "=f"(v.x), "=f"(v.y), "=f"(v.z), "=f"(v.w) : "l"(p));
    return v;
}

__global__ __launch_bounds__(NTHR) void spline_mse_r8(
    const float* __restrict__ yt, const float* __restrict__ yp,
    float* __restrict__ out)
{
    const int s = blockIdx.x >> 2;             // 0..102
    const int q = blockIdx.x & 3;              // batch group [32q, 32q+32)
    const int d4   = threadIdx.x & (D4_ - 1);
    const int brel = threadIdx.x >> 4;         // 0..31

    const int addr = s * 10 * D4_ + (q * 32 + brel) * ROW_STRIDE4_ + d4;
    const float4 va = ldg_256b((const float4*)yt + addr);
    const float4 vb = ldg_256b((const float4*)yp + addr);

    float e0 = va.x - vb.x;
    float e1 = va.y - vb.y;
    float e2 = va.z - vb.z;
    float e3 = va.w - vb.w;
    float acc = e0 * e0;
    acc = fmaf(e1, e1, acc);
    acc = fmaf(e2, e2, acc);
    acc = fmaf(e3, e3, acc);

    // block reduce (fixed order -> deterministic)
    #pragma unroll
    for (int o = 16; o > 0; o >>= 1)
        acc += __shfl_down_sync(0xffffffffu, acc, o);

    __shared__ float sh[NTHR / 32];
    if ((threadIdx.x & 31) == 0) sh[threadIdx.x >> 5] = acc;
    __syncthreads();

    if (threadIdx.x != 0) return;              // thread 0 only past here

    float v = sh[0];
    #pragma unroll
    for (int w = 1; w < NTHR / 32; w++) v += sh[w];

    // level 1: bin atomic (103 blocks per address, 4 addresses in parallel)
    unsigned long long fixed =
        __double2ull_rn((double)v * FIX_SCALE);          // v >= 0, exact int
    unsigned long long* bin = &g_bins[(blockIdx.x & (NBINS - 1)) * 32];
    unsigned long long old = atomicAdd(bin, (fixed << 16) | 1ull);

    if ((old & 0xFFFFull) != (unsigned long long)(BINSZ - 1)) return;

    // bin-last: forward exact bin total, reset bin for next replay
    unsigned long long bin_total = (old >> 16) + fixed;
    *bin = 0ull;                                         // no later readers
    unsigned long long fold = atomicAdd(&g_final, (bin_total << 16) | 1ull);

    if ((fold & 0xFFFFull) == (unsigned long long)(NBINS - 1)) {
        unsigned long long total = (fold >> 16) + bin_total;
        out[0] = (float)((double)total / (FIX_SCALE * COUNT_));
        g_final = 0ull;                                  // reset for replay
    }
}

extern "C" void kernel_launch(void* const* d_in, const int* in_sizes, int n_in,
                              void* d_out, int out_size)
{
    const float* yt = (const float*)d_in[0];   // true_frames
    const float* yp = (const float*)d_in[1];   // predicted_frames
    spline_mse_r8<<<NBLK, NTHR>>>(yt, yp, (float*)d_out);
}